// round 12
// baseline (speedup 1.0000x reference)
#include <cuda_runtime.h>
#include <math.h>

#define BB 4
#define NN 20000
#define MM 1024
#define CAP 1024
#define KSEL 50
#define SEL_BLOCKS 512   // k_select blocks (8 warps = 8 nodes each)

// k_assign tiling: 320 threads = 80 point-pairs x 4 kp-chunks of 256
#define PAIRS 80
#define PTSB  160        // points per block
#define CHUNKS 4
#define MCH   256        // kps per chunk
#define SUB   64         // sub-block for argmin rescan
#define NSUB  4          // MCH/SUB

typedef unsigned long long ull;

// scratch (device globals — allocation-free). BSS zero at process start;
// the last k_select block re-zeros g_count and g_ticket every launch.
__device__ int    g_count[BB*MM];
__device__ int    g_p2n[BB*NN];
__device__ float  g_tp[BB*NN*3];
__device__ int    g_bidx[BB*MM*CAP];
__device__ float  g_bdist[BB*MM*CAP];
__device__ long long g_pnum[SEL_BLOCKS];
__device__ long long g_pden[SEL_BLOCKS];
__device__ unsigned g_ticket;

__device__ __forceinline__ ull f2fma(ull a, ull b, ull c) {
    ull d;
    asm("fma.rn.f32x2 %0, %1, %2, %3;" : "=l"(d) : "l"(a), "l"(b), "l"(c));
    return d;
}
__device__ __forceinline__ ull packf2(float lo, float hi) {
    ull d;
    asm("mov.b64 %0, {%1, %2};" : "=l"(d) : "f"(lo), "f"(hi));
    return d;
}

// ---------------------------------------------------------------------------
// Kernel 1: nearest keypoint per point. 2 points/thread via packed f32x2 FMA;
// the 1024 keypoints are split 4 ways across chunk-threads (occupancy), and
// the inner loop is MIN-ONLY (no index tracking): we track the winning 64-wide
// sub-block and recover the exact argmin index with a bit-equal rescan.
// Chunks are combined in ascending order with strict '<' => exact
// first-occurrence semantics, independent of thread timing.
// ---------------------------------------------------------------------------
__global__ void __launch_bounds__(320) k_assign(const float* __restrict__ pts,
                                                const float* __restrict__ kp,
                                                const float* __restrict__ pose) {
    __shared__ float4 sA[MM];           // (-2x,-2x,-2y,-2y)
    __shared__ float4 sB[MM];           // (-2z,-2z, ss, ss)
    __shared__ float  sbest[CHUNKS][PTSB];
    __shared__ int    sbi  [CHUNKS][PTSB];

    const int b = blockIdx.y;
    const float* kpb = kp + (size_t)b * MM * 3;
    for (int i = threadIdx.x; i < MM; i += 320) {
        float x = kpb[3*i+0], y = kpb[3*i+1], z = kpb[3*i+2];
        float ss = fmaf(x,x, fmaf(y,y, z*z));
        sA[i] = make_float4(-2.f*x, -2.f*x, -2.f*y, -2.f*y);
        sB[i] = make_float4(-2.f*z, -2.f*z, ss, ss);
    }
    __syncthreads();

    const int t  = threadIdx.x;
    const int ch = t / PAIRS;           // kp chunk 0..3
    const int pr = t - ch * PAIRS;      // point pair 0..79
    const int n0 = blockIdx.x * PTSB + pr * 2;   // 125*160 == 20000 exactly

    const float* p = pts + ((size_t)b * NN + n0) * 3;
    const float2 q0 = ((const float2*)p)[0];
    const float2 q1 = ((const float2*)p)[1];
    const float2 q2 = ((const float2*)p)[2];
    const float px0 = q0.x, py0 = q0.y, pz0 = q1.x;
    const float px1 = q1.y, py1 = q2.x, pz1 = q2.y;

    const ull px2 = packf2(px0, px1);
    const ull py2 = packf2(py0, py1);
    const ull pz2 = packf2(pz0, pz1);

    const ulonglong2* __restrict__ A2 = (const ulonglong2*)sA;
    const ulonglong2* __restrict__ B2 = (const ulonglong2*)sB;

    float best0 = 3.4e38f, best1 = 3.4e38f;
    int   blk0 = 0, blk1 = 0;
    const int mb = ch * MCH;

    #pragma unroll
    for (int sb = 0; sb < NSUB; sb++) {
        float l0 = 3.4e38f, l1 = 3.4e38f;
        const int base = mb + sb * SUB;
        #pragma unroll 8
        for (int mm = 0; mm < SUB; mm++) {
            ulonglong2 a = A2[base + mm];
            ulonglong2 c = B2[base + mm];
            ull acc = f2fma(a.x, px2, c.y);
            acc = f2fma(a.y, py2, acc);
            acc = f2fma(c.x, pz2, acc);
            l0 = fminf(l0, __uint_as_float((unsigned)acc));
            l1 = fminf(l1, __uint_as_float((unsigned)(acc >> 32)));
        }
        if (l0 < best0) { best0 = l0; blk0 = sb; }
        if (l1 < best1) { best1 = l1; blk1 = sb; }
    }

    // exact index recovery: rescan winning 64-sub-block, first bit-equal match
    int bi0 = 0x7fffffff, bi1 = 0x7fffffff;
    {
        const int base = mb + blk0 * SUB;
        #pragma unroll 8
        for (int mm = 0; mm < SUB; mm++) {
            float4 a = sA[base + mm];
            float4 c = sB[base + mm];
            float s = fmaf(c.x, pz0, fmaf(a.z, py0, fmaf(a.x, px0, c.z)));
            if (s == best0) bi0 = min(bi0, base + mm);
        }
    }
    {
        const int base = mb + blk1 * SUB;
        #pragma unroll 8
        for (int mm = 0; mm < SUB; mm++) {
            float4 a = sA[base + mm];
            float4 c = sB[base + mm];
            float s = fmaf(c.x, pz1, fmaf(a.z, py1, fmaf(a.x, px1, c.z)));
            if (s == best1) bi1 = min(bi1, base + mm);
        }
    }

    sbest[ch][pr*2+0] = best0;  sbi[ch][pr*2+0] = bi0;
    sbest[ch][pr*2+1] = best1;  sbi[ch][pr*2+1] = bi1;
    __syncthreads();

    if (ch == 0) {
        // combine chunks in ascending order, strict '<' => earliest chunk wins ties
        #pragma unroll
        for (int cx = 1; cx < CHUNKS; cx++) {
            float v0 = sbest[cx][pr*2+0];
            float v1 = sbest[cx][pr*2+1];
            if (v0 < best0) { best0 = v0; bi0 = sbi[cx][pr*2+0]; }
            if (v1 < best1) { best1 = v1; bi1 = sbi[cx][pr*2+1]; }
        }

        const float* P = pose + b * 16;
        float R00=P[0],R01=P[1],R02=P[2],T0=P[3];
        float R10=P[4],R11=P[5],R12=P[6],T1=P[7];
        float R20=P[8],R21=P[9],R22=P[10],T2=P[11];

        // point 0
        {
            float psq = fmaf(px0,px0, fmaf(py0,py0, pz0*pz0));
            float dist = best0 + psq;
            g_p2n[b*NN + n0] = bi0;
            int pos = atomicAdd(&g_count[b*MM + bi0], 1);
            if (pos < CAP) {
                g_bidx [(size_t)(b*MM + bi0) * CAP + pos] = n0;
                g_bdist[(size_t)(b*MM + bi0) * CAP + pos] = dist;
            }
        }
        // point 1
        {
            float psq = fmaf(px1,px1, fmaf(py1,py1, pz1*pz1));
            float dist = best1 + psq;
            g_p2n[b*NN + n0 + 1] = bi1;
            int pos = atomicAdd(&g_count[b*MM + bi1], 1);
            if (pos < CAP) {
                g_bidx [(size_t)(b*MM + bi1) * CAP + pos] = n0 + 1;
                g_bdist[(size_t)(b*MM + bi1) * CAP + pos] = dist;
            }
        }

        float t0x = fmaf(R00,px0, fmaf(R01,py0, fmaf(R02,pz0, T0)));
        float t0y = fmaf(R10,px0, fmaf(R11,py0, fmaf(R12,pz0, T1)));
        float t0z = fmaf(R20,px0, fmaf(R21,py0, fmaf(R22,pz0, T2)));
        float t1x = fmaf(R00,px1, fmaf(R01,py1, fmaf(R02,pz1, T0)));
        float t1y = fmaf(R10,px1, fmaf(R11,py1, fmaf(R12,pz1, T1)));
        float t1z = fmaf(R20,px1, fmaf(R21,py1, fmaf(R22,pz1, T2)));
        float2* tv = (float2*)(g_tp + ((size_t)b * NN + n0) * 3);
        tv[0] = make_float2(t0x, t0y);
        tv[1] = make_float2(t0z, t1x);
        tv[2] = make_float2(t1y, t1z);
    }
}

// orderable packing of (dist, idx) for lexicographic min via u64
__device__ __forceinline__ ull packdi(float d, int i) {
    unsigned int b = __float_as_uint(d);
    b = (b & 0x80000000u) ? ~b : (b | 0x80000000u);
    return ((ull)b << 32) | (unsigned int)i;
}

// ---------------------------------------------------------------------------
// Kernel 2: ONE WARP PER NODE (8 nodes/block) + fused deterministic final
// reduction (atomic ticket, last block sums 512 integer partials in fixed
// order, writes output, re-zeros g_count and the ticket).
// ---------------------------------------------------------------------------
__global__ void __launch_bounds__(256) k_select(const float* __restrict__ kpw,
                                                const float* __restrict__ ow,
                                                float* __restrict__ out) {
    __shared__ long long s_num[8];
    __shared__ long long s_den[8];
    __shared__ int s_last;

    const int warp = threadIdx.x >> 5;
    const int lane = threadIdx.x & 31;
    const int id   = blockIdx.x * 8 + warp;     // node id, exactly BB*MM
    const int b    = id >> 10;
    const int m    = id & (MM - 1);

    const int c  = g_count[id];
    const int cc = min(c, CAP);
    const int*   bidx  = &g_bidx [(size_t)id * CAP];
    const float* bdist = &g_bdist[(size_t)id * CAP];
    const float* tpf   = g_tp + (size_t)b * NN * 3;

    float sx = 0.f, sy = 0.f, sz = 0.f;

    if (c <= KSEL) {
        // ---- bitonic sort of 64 index keys (INT_MAX padded), ascending ----
        int v0 = (lane      < cc) ? bidx[lane]      : 0x7fffffff;
        int v1 = (lane + 32 < cc) ? bidx[lane + 32] : 0x7fffffff;
        #pragma unroll
        for (int k = 2; k <= 32; k <<= 1) {
            #pragma unroll
            for (int j = k >> 1; j >= 1; j >>= 1) {
                bool up0 = ((lane & k) == 0);
                bool up1 = (((lane + 32) & k) == 0);
                bool low = ((lane & j) == 0);
                int o0 = __shfl_xor_sync(0xffffffffu, v0, j);
                int o1 = __shfl_xor_sync(0xffffffffu, v1, j);
                v0 = (low == up0) ? min(v0, o0) : max(v0, o0);
                v1 = (low == up1) ? min(v1, o1) : max(v1, o1);
            }
        }
        {   // k = 64 merge
            int lo_ = min(v0, v1), hi_ = max(v0, v1); v0 = lo_; v1 = hi_;
            #pragma unroll
            for (int j = 16; j >= 1; j >>= 1) {
                bool low = ((lane & j) == 0);
                int o0 = __shfl_xor_sync(0xffffffffu, v0, j);
                int o1 = __shfl_xor_sync(0xffffffffu, v1, j);
                v0 = low ? min(v0, o0) : max(v0, o0);
                v1 = low ? min(v1, o1) : max(v1, o1);
            }
        }
        float ax = 0.f, ay = 0.f, az = 0.f;
        if (lane < cc) {
            const float* tt = tpf + (size_t)v0 * 3;
            ax += tt[0]; ay += tt[1]; az += tt[2];
        }
        if (lane + 32 < cc) {
            const float* tt = tpf + (size_t)v1 * 3;
            ax += tt[0]; ay += tt[1]; az += tt[2];
        }
        #pragma unroll
        for (int off = 16; off > 0; off >>= 1) {
            ax += __shfl_xor_sync(0xffffffffu, ax, off);
            ay += __shfl_xor_sync(0xffffffffu, ay, off);
            az += __shfl_xor_sync(0xffffffffu, az, off);
        }
        sx += ax; sy += ay; sz += az;

        // ---- pad with smallest UNassigned indices (ballot scan) ----
        int k = KSEL - c;
        const int* p2n = &g_p2n[b * NN];
        int n0 = 0;
        while (k > 0) {
            int n = n0 + lane;
            int pm = (n < NN) ? p2n[n] : m;
            bool un = (pm != m);
            unsigned mask = __ballot_sync(0xffffffffu, un);
            int cnt  = __popc(mask);
            int take = min(k, cnt);
            int rank = __popc(mask & ((1u << lane) - 1u));
            bool sel = un && (rank < take);
            float tx = 0.f, ty = 0.f, tz = 0.f;
            if (sel) {
                const float* tt = tpf + (size_t)n * 3;
                tx = tt[0]; ty = tt[1]; tz = tt[2];
            }
            #pragma unroll
            for (int off = 16; off > 0; off >>= 1) {
                tx += __shfl_xor_sync(0xffffffffu, tx, off);
                ty += __shfl_xor_sync(0xffffffffu, ty, off);
                tz += __shfl_xor_sync(0xffffffffu, tz, off);
            }
            sx += tx; sy += ty; sz += tz;
            k -= take;
            n0 += 32;
        }
    } else {
        // rare: 50 smallest by (dist, idx), extracted in that order
        ull last = 0ull;
        for (int r = 0; r < KSEL; r++) {
            ull mn = 0xffffffffffffffffull;
            for (int base = 0; base < cc; base += 32) {
                int j = base + lane;
                ull key = (j < cc) ? packdi(bdist[j], bidx[j])
                                   : 0xffffffffffffffffull;
                if (key <= last) key = 0xffffffffffffffffull;
                mn = min(mn, key);
            }
            #pragma unroll
            for (int off = 16; off > 0; off >>= 1) {
                ull o = __shfl_xor_sync(0xffffffffu, mn, off);
                mn = min(mn, o);
            }
            last = mn;
            int selN = (int)(mn & 0xffffffffu);
            const float* tt = tpf + (size_t)selN * 3;
            sx += tt[0]; sy += tt[1]; sz += tt[2];
        }
    }

    if (lane == 0) {
        const float inv = 1.0f / (float)KSEL;
        const float* kw = kpw + (size_t)id * 3;
        float ex = sx * inv - kw[0];
        float ey = sy * inv - kw[1];
        float ez = sz * inv - kw[2];
        float l1 = fabsf(ex) + fabsf(ey) + fabsf(ez);
        double w = (double)ow[id];
        // Q32 fixed point: integer sums are order-free => deterministic
        s_num[warp] = (long long)(w * (double)l1 * 4294967296.0);
        s_den[warp] = (long long)(w * 4294967296.0);
    }
    __syncthreads();
    if (threadIdx.x == 0) {
        long long n = 0, d = 0;
        #pragma unroll
        for (int i = 0; i < 8; i++) { n += s_num[i]; d += s_den[i]; }
        g_pnum[blockIdx.x] = n;
        g_pden[blockIdx.x] = d;
        __threadfence();
        s_last = (atomicAdd(&g_ticket, 1u) == (unsigned)(gridDim.x - 1));
    }
    __syncthreads();

    if (s_last) {
        // fixed-order integer reduction over 512 partials (deterministic)
        __shared__ long long rn[256];
        __shared__ long long rd[256];
        const int t = threadIdx.x;
        rn[t] = g_pnum[t] + g_pnum[t + 256];
        rd[t] = g_pden[t] + g_pden[t + 256];
        __syncthreads();
        for (int s = 128; s > 0; s >>= 1) {
            if (t < s) { rn[t] += rn[t + s]; rd[t] += rd[t + s]; }
            __syncthreads();
        }
        if (t == 0) {
            double num = (double)rn[0] * (1.0 / 4294967296.0);
            double den = (double)rd[0] * (1.0 / 4294967296.0);
            out[0] = (float)(num / fmax(den, 1e-6));
        }
        // restore invariants for the next launch / graph replay
        for (int i = t; i < BB*MM; i += 256) g_count[i] = 0;
        __syncthreads();
        if (t == 0) g_ticket = 0;
    }
}

extern "C" void kernel_launch(void* const* d_in, const int* in_sizes, int n_in,
                              void* d_out, int out_size) {
    const float* pts  = (const float*)d_in[0];  // (B,N,3)
    const float* kp   = (const float*)d_in[1];  // (B,M,3)
    const float* kpw  = (const float*)d_in[2];  // (B,M,3)
    const float* pose = (const float*)d_in[3];  // (B,4,4)
    const float* ow   = (const float*)d_in[4];  // (B,M)
    float* out = (float*)d_out;

    dim3 g1(NN / PTSB, BB);                 // 125 x 4 blocks, 320 threads
    k_assign<<<g1, 320>>>(pts, kp, pose);

    k_select<<<SEL_BLOCKS, 256>>>(kpw, ow, out);
}

// round 13
// speedup vs baseline: 2.5743x; 2.5743x over previous
#include <cuda_runtime.h>
#include <math.h>

#define BB 4
#define NN 20000
#define MM 1024
#define CAP 1024
#define KSEL 50
#define SEL_BLOCKS 512   // k_select blocks (8 warps = 8 nodes each)

#define PPT 4            // points per thread in k_assign
#define SUB 16           // kp sub-block for argmin rescan
#define NSUB 64          // MM/SUB
#define SKSTRIDE 17      // float4 stride per sub-block (16 + 1 skew)

typedef unsigned long long ull;

// scratch (device globals — allocation-free). BSS zero at process start;
// the last k_select block re-zeros g_count and g_ticket every launch.
__device__ int    g_count[BB*MM];
__device__ int    g_p2n[BB*NN];
__device__ float  g_tp[BB*NN*3];
__device__ ull    g_bkey[BB*MM*CAP];     // packed (orderable dist, idx)
__device__ long long g_pnum[SEL_BLOCKS];
__device__ long long g_pden[SEL_BLOCKS];
__device__ unsigned g_ticket;

__device__ __forceinline__ ull f2fma(ull a, ull b, ull c) {
    ull d;
    asm("fma.rn.f32x2 %0, %1, %2, %3;" : "=l"(d) : "l"(a), "l"(b), "l"(c));
    return d;
}
__device__ __forceinline__ ull packf2(float lo, float hi) {
    ull d;
    asm("mov.b64 %0, {%1, %2};" : "=l"(d) : "f"(lo), "f"(hi));
    return d;
}
__device__ __forceinline__ float2 unpackf2(ull v) {
    float2 f;
    asm("mov.b64 {%0, %1}, %2;" : "=f"(f.x), "=f"(f.y) : "l"(v));
    return f;
}
// orderable packing of (dist, idx): u64 ascending == (dist, idx) lexicographic
__device__ __forceinline__ ull packdi(float d, int i) {
    unsigned int b = __float_as_uint(d);
    b = (b & 0x80000000u) ? ~b : (b | 0x80000000u);
    return ((ull)b << 32) | (unsigned int)i;
}

// ---------------------------------------------------------------------------
// Kernel 1: nearest keypoint per point. 4 points/thread; keypoints in smem as
// UNduplicated float4 (-2x,-2y,-2z,|kp|^2) with a 16B skew per 16-entry
// sub-block (bank-staggers the rescan; main loop reads are broadcast).
// Inner loop is min-only (3 FFMA2 + 4 FMNMX per kp for 4 points); the winning
// sub-block per point is rescanned with the IDENTICAL fma order (bit-exact)
// to recover the first-occurrence argmin index.
// ---------------------------------------------------------------------------
__global__ void __launch_bounds__(128) k_assign(const float* __restrict__ pts,
                                                const float* __restrict__ kp,
                                                const float* __restrict__ pose) {
    __shared__ float4 kp4[MM + NSUB];   // skewed: idx = m + (m>>4)

    const int b = blockIdx.y;
    const float* kpb = kp + (size_t)b * MM * 3;
    for (int i = threadIdx.x; i < MM; i += 128) {
        float x = kpb[3*i+0], y = kpb[3*i+1], z = kpb[3*i+2];
        float ss = fmaf(x,x, fmaf(y,y, z*z));
        kp4[i + (i >> 4)] = make_float4(-2.f*x, -2.f*y, -2.f*z, ss);
    }
    __syncthreads();

    const int t  = blockIdx.x * 128 + threadIdx.x;
    const int n0 = t * PPT;
    if (n0 >= NN) return;

    // 4 consecutive points = 12 floats = 3 aligned float4
    const float4* pv = (const float4*)(pts + ((size_t)b * NN + n0) * 3);
    float4 A = pv[0], Bq = pv[1], C = pv[2];
    const float px0=A.x,  py0=A.y,  pz0=A.z;
    const float px1=A.w,  py1=Bq.x, pz1=Bq.y;
    const float px2=Bq.z, py2=Bq.w, pz2=C.x;
    const float px3=C.y,  py3=C.z,  pz3=C.w;

    const ull px01 = packf2(px0,px1), px23 = packf2(px2,px3);
    const ull py01 = packf2(py0,py1), py23 = packf2(py2,py3);
    const ull pz01 = packf2(pz0,pz1), pz23 = packf2(pz2,pz3);

    float best0=3.4e38f, best1=3.4e38f, best2=3.4e38f, best3=3.4e38f;
    int   blk0=0, blk1=0, blk2=0, blk3=0;

    for (int sb = 0; sb < NSUB; sb++) {
        const float4* base = kp4 + sb * SKSTRIDE;
        float l0=3.4e38f, l1=3.4e38f, l2=3.4e38f, l3=3.4e38f;
        #pragma unroll
        for (int mm = 0; mm < SUB; mm++) {
            float4 k = base[mm];
            ull kx2 = packf2(k.x, k.x);
            ull ky2 = packf2(k.y, k.y);
            ull kz2 = packf2(k.z, k.z);
            ull kw2 = packf2(k.w, k.w);
            ull a = f2fma(kx2, px01, kw2);
            a = f2fma(ky2, py01, a);
            a = f2fma(kz2, pz01, a);
            ull c = f2fma(kx2, px23, kw2);
            c = f2fma(ky2, py23, c);
            c = f2fma(kz2, pz23, c);
            float2 fa = unpackf2(a);
            float2 fc = unpackf2(c);
            l0 = fminf(l0, fa.x); l1 = fminf(l1, fa.y);
            l2 = fminf(l2, fc.x); l3 = fminf(l3, fc.y);
        }
        if (l0 < best0) { best0 = l0; blk0 = sb; }
        if (l1 < best1) { best1 = l1; blk1 = sb; }
        if (l2 < best2) { best2 = l2; blk2 = sb; }
        if (l3 < best3) { best3 = l3; blk3 = sb; }
    }

    // exact index recovery: rescan winning sub-block, identical fma order
    int bi[PPT];
    float bpx[PPT] = {px0,px1,px2,px3};
    float bpy[PPT] = {py0,py1,py2,py3};
    float bpz[PPT] = {pz0,pz1,pz2,pz3};
    float bbest[PPT] = {best0,best1,best2,best3};
    int   bblk[PPT] = {blk0,blk1,blk2,blk3};
    #pragma unroll
    for (int j = 0; j < PPT; j++) {
        const float4* base = kp4 + bblk[j] * SKSTRIDE;
        int r = 0x7fffffff;
        #pragma unroll
        for (int mm = 0; mm < SUB; mm++) {
            float4 k = base[mm];
            float s = fmaf(k.z, bpz[j], fmaf(k.y, bpy[j], fmaf(k.x, bpx[j], k.w)));
            if (s == bbest[j]) r = min(r, bblk[j] * SUB + mm);
        }
        bi[j] = r;
    }

    const float* P = pose + b * 16;
    float R00=P[0],R01=P[1],R02=P[2],T0=P[3];
    float R10=P[4],R11=P[5],R12=P[6],T1=P[7];
    float R20=P[8],R21=P[9],R22=P[10],T2=P[11];

    float tp[12];
    #pragma unroll
    for (int j = 0; j < PPT; j++) {
        const int n = n0 + j;
        float psq = fmaf(bpx[j],bpx[j], fmaf(bpy[j],bpy[j], bpz[j]*bpz[j]));
        float dist = bbest[j] + psq;
        g_p2n[b*NN + n] = bi[j];
        int pos = atomicAdd(&g_count[b*MM + bi[j]], 1);
        if (pos < CAP)
            g_bkey[(size_t)(b*MM + bi[j]) * CAP + pos] = packdi(dist, n);
        tp[3*j+0] = fmaf(R00,bpx[j], fmaf(R01,bpy[j], fmaf(R02,bpz[j], T0)));
        tp[3*j+1] = fmaf(R10,bpx[j], fmaf(R11,bpy[j], fmaf(R12,bpz[j], T1)));
        tp[3*j+2] = fmaf(R20,bpx[j], fmaf(R21,bpy[j], fmaf(R22,bpz[j], T2)));
    }
    float4* tv = (float4*)(g_tp + ((size_t)b * NN + n0) * 3);
    tv[0] = make_float4(tp[0],tp[1],tp[2],tp[3]);
    tv[1] = make_float4(tp[4],tp[5],tp[6],tp[7]);
    tv[2] = make_float4(tp[8],tp[9],tp[10],tp[11]);
}

// ---- warp bitonic helpers: 64 keys in (v0 rank=lane, v1 rank=32+lane) ----
__device__ __forceinline__ void bsort64(ull& v0, ull& v1, int lane) {
    #pragma unroll
    for (int k = 2; k <= 32; k <<= 1) {
        #pragma unroll
        for (int j = k >> 1; j >= 1; j >>= 1) {
            bool up0 = ((lane & k) == 0);
            bool up1 = (((lane + 32) & k) == 0);
            bool low = ((lane & j) == 0);
            ull o0 = __shfl_xor_sync(0xffffffffu, v0, j);
            ull o1 = __shfl_xor_sync(0xffffffffu, v1, j);
            v0 = (low == up0) ? min(v0, o0) : max(v0, o0);
            v1 = (low == up1) ? min(v1, o1) : max(v1, o1);
        }
    }
    ull lo_ = min(v0, v1), hi_ = max(v0, v1); v0 = lo_; v1 = hi_;
    #pragma unroll
    for (int j = 16; j >= 1; j >>= 1) {
        bool low = ((lane & j) == 0);
        ull o0 = __shfl_xor_sync(0xffffffffu, v0, j);
        ull o1 = __shfl_xor_sync(0xffffffffu, v1, j);
        v0 = low ? min(v0, o0) : max(v0, o0);
        v1 = low ? min(v1, o1) : max(v1, o1);
    }
}
// both (v0,v1) and (t0,t1) sorted ascending; result: lowest 64, sorted asc.
__device__ __forceinline__ void bmerge_low64(ull& v0, ull& v1, ull t0, ull t1,
                                             int lane) {
    ull r0 = __shfl_xor_sync(0xffffffffu, t1, 31);  // tile rank 63-lane
    ull r1 = __shfl_xor_sync(0xffffffffu, t0, 31);  // tile rank 31-lane
    v0 = min(v0, r0);
    v1 = min(v1, r1);
    ull lo_ = min(v0, v1), hi_ = max(v0, v1); v0 = lo_; v1 = hi_;
    #pragma unroll
    for (int j = 16; j >= 1; j >>= 1) {
        bool low = ((lane & j) == 0);
        ull o0 = __shfl_xor_sync(0xffffffffu, v0, j);
        ull o1 = __shfl_xor_sync(0xffffffffu, v1, j);
        v0 = low ? min(v0, o0) : max(v0, o0);
        v1 = low ? min(v1, o1) : max(v1, o1);
    }
}

// ---------------------------------------------------------------------------
// Kernel 2: ONE WARP PER NODE (8 nodes/block) + fused deterministic final
// reduction. c<=50: bitonic-sort indices + ballot-scan padding. c>50:
// streaming bitonic top-64 merge over (dist,idx) keys, sum smallest 50.
// All sums use canonical orders => deterministic.
// ---------------------------------------------------------------------------
__global__ void __launch_bounds__(256) k_select(const float* __restrict__ kpw,
                                                const float* __restrict__ ow,
                                                float* __restrict__ out) {
    __shared__ long long s_num[8];
    __shared__ long long s_den[8];
    __shared__ int s_last;

    const int warp = threadIdx.x >> 5;
    const int lane = threadIdx.x & 31;
    const int id   = blockIdx.x * 8 + warp;
    const int b    = id >> 10;
    const int m    = id & (MM - 1);

    const int c  = g_count[id];
    const int cc = min(c, CAP);
    const ull* bkey = &g_bkey[(size_t)id * CAP];
    const float* tpf = g_tp + (size_t)b * NN * 3;

    float sx = 0.f, sy = 0.f, sz = 0.f;

    if (c <= KSEL) {
        // ---- bitonic sort of 64 index keys (INT_MAX padded), ascending ----
        int v0 = (lane      < cc) ? (int)(unsigned)bkey[lane]      : 0x7fffffff;
        int v1 = (lane + 32 < cc) ? (int)(unsigned)bkey[lane + 32] : 0x7fffffff;
        #pragma unroll
        for (int k = 2; k <= 32; k <<= 1) {
            #pragma unroll
            for (int j = k >> 1; j >= 1; j >>= 1) {
                bool up0 = ((lane & k) == 0);
                bool up1 = (((lane + 32) & k) == 0);
                bool low = ((lane & j) == 0);
                int o0 = __shfl_xor_sync(0xffffffffu, v0, j);
                int o1 = __shfl_xor_sync(0xffffffffu, v1, j);
                v0 = (low == up0) ? min(v0, o0) : max(v0, o0);
                v1 = (low == up1) ? min(v1, o1) : max(v1, o1);
            }
        }
        {
            int lo_ = min(v0, v1), hi_ = max(v0, v1); v0 = lo_; v1 = hi_;
            #pragma unroll
            for (int j = 16; j >= 1; j >>= 1) {
                bool low = ((lane & j) == 0);
                int o0 = __shfl_xor_sync(0xffffffffu, v0, j);
                int o1 = __shfl_xor_sync(0xffffffffu, v1, j);
                v0 = low ? min(v0, o0) : max(v0, o0);
                v1 = low ? min(v1, o1) : max(v1, o1);
            }
        }
        float ax = 0.f, ay = 0.f, az = 0.f;
        if (lane < cc) {
            const float* tt = tpf + (size_t)v0 * 3;
            ax += tt[0]; ay += tt[1]; az += tt[2];
        }
        if (lane + 32 < cc) {
            const float* tt = tpf + (size_t)v1 * 3;
            ax += tt[0]; ay += tt[1]; az += tt[2];
        }
        #pragma unroll
        for (int off = 16; off > 0; off >>= 1) {
            ax += __shfl_xor_sync(0xffffffffu, ax, off);
            ay += __shfl_xor_sync(0xffffffffu, ay, off);
            az += __shfl_xor_sync(0xffffffffu, az, off);
        }
        sx += ax; sy += ay; sz += az;

        // ---- pad with smallest UNassigned indices (ballot scan) ----
        int k = KSEL - c;
        const int* p2n = &g_p2n[b * NN];
        int n0 = 0;
        while (k > 0) {
            int n = n0 + lane;
            int pm = (n < NN) ? p2n[n] : m;
            bool un = (pm != m);
            unsigned mask = __ballot_sync(0xffffffffu, un);
            int cnt  = __popc(mask);
            int take = min(k, cnt);
            int rank = __popc(mask & ((1u << lane) - 1u));
            bool sel = un && (rank < take);
            float tx = 0.f, ty = 0.f, tz = 0.f;
            if (sel) {
                const float* tt = tpf + (size_t)n * 3;
                tx = tt[0]; ty = tt[1]; tz = tt[2];
            }
            #pragma unroll
            for (int off = 16; off > 0; off >>= 1) {
                tx += __shfl_xor_sync(0xffffffffu, tx, off);
                ty += __shfl_xor_sync(0xffffffffu, ty, off);
                tz += __shfl_xor_sync(0xffffffffu, tz, off);
            }
            sx += tx; sy += ty; sz += tz;
            k -= take;
            n0 += 32;
        }
    } else {
        // ---- streaming bitonic top-64 by (dist,idx); sum smallest 50 ----
        const ull UMAX = 0xffffffffffffffffull;
        ull v0 = (lane      < cc) ? bkey[lane]      : UMAX;
        ull v1 = (lane + 32 < cc) ? bkey[lane + 32] : UMAX;
        bsort64(v0, v1, lane);
        for (int base = 64; base < cc; base += 64) {
            ull t0 = (base + lane      < cc) ? bkey[base + lane]      : UMAX;
            ull t1 = (base + lane + 32 < cc) ? bkey[base + lane + 32] : UMAX;
            bsort64(t0, t1, lane);
            bmerge_low64(v0, v1, t0, t1, lane);
        }
        // ranks 0..31 in v0 (all <= 49), ranks 32..63 in v1 (take lane<=17)
        float ax, ay, az;
        {
            int i0 = (int)(unsigned)v0;       // rank lane <= 31 < cc, real
            const float* tt = tpf + (size_t)i0 * 3;
            ax = tt[0]; ay = tt[1]; az = tt[2];
        }
        if (lane + 32 <= KSEL - 1) {          // ranks 32..49, cc > 50 => real
            int i1 = (int)(unsigned)v1;
            const float* tt = tpf + (size_t)i1 * 3;
            ax += tt[0]; ay += tt[1]; az += tt[2];
        }
        #pragma unroll
        for (int off = 16; off > 0; off >>= 1) {
            ax += __shfl_xor_sync(0xffffffffu, ax, off);
            ay += __shfl_xor_sync(0xffffffffu, ay, off);
            az += __shfl_xor_sync(0xffffffffu, az, off);
        }
        sx += ax; sy += ay; sz += az;
    }

    if (lane == 0) {
        const float inv = 1.0f / (float)KSEL;
        const float* kw = kpw + (size_t)id * 3;
        float ex = sx * inv - kw[0];
        float ey = sy * inv - kw[1];
        float ez = sz * inv - kw[2];
        float l1 = fabsf(ex) + fabsf(ey) + fabsf(ez);
        double w = (double)ow[id];
        // Q32 fixed point: integer sums are order-free => deterministic
        s_num[warp] = (long long)(w * (double)l1 * 4294967296.0);
        s_den[warp] = (long long)(w * 4294967296.0);
    }
    __syncthreads();
    if (threadIdx.x == 0) {
        long long n = 0, d = 0;
        #pragma unroll
        for (int i = 0; i < 8; i++) { n += s_num[i]; d += s_den[i]; }
        g_pnum[blockIdx.x] = n;
        g_pden[blockIdx.x] = d;
        __threadfence();
        s_last = (atomicAdd(&g_ticket, 1u) == (unsigned)(gridDim.x - 1));
    }
    __syncthreads();

    if (s_last) {
        __shared__ long long rn[256];
        __shared__ long long rd[256];
        const int t = threadIdx.x;
        rn[t] = g_pnum[t] + g_pnum[t + 256];
        rd[t] = g_pden[t] + g_pden[t + 256];
        __syncthreads();
        for (int s = 128; s > 0; s >>= 1) {
            if (t < s) { rn[t] += rn[t + s]; rd[t] += rd[t + s]; }
            __syncthreads();
        }
        if (t == 0) {
            double num = (double)rn[0] * (1.0 / 4294967296.0);
            double den = (double)rd[0] * (1.0 / 4294967296.0);
            out[0] = (float)(num / fmax(den, 1e-6));
        }
        // restore invariants for the next launch / graph replay
        for (int i = t; i < BB*MM; i += 256) g_count[i] = 0;
        __syncthreads();
        if (t == 0) g_ticket = 0;
    }
}

extern "C" void kernel_launch(void* const* d_in, const int* in_sizes, int n_in,
                              void* d_out, int out_size) {
    const float* pts  = (const float*)d_in[0];  // (B,N,3)
    const float* kp   = (const float*)d_in[1];  // (B,M,3)
    const float* kpw  = (const float*)d_in[2];  // (B,M,3)
    const float* pose = (const float*)d_in[3];  // (B,4,4)
    const float* ow   = (const float*)d_in[4];  // (B,M)
    float* out = (float*)d_out;

    dim3 g1((NN/PPT + 127) / 128, BB);          // 40 x 4 blocks, 128 threads
    k_assign<<<g1, 128>>>(pts, kp, pose);

    k_select<<<SEL_BLOCKS, 256>>>(kpw, ow, out);
}